// round 5
// baseline (speedup 1.0000x reference)
#include <cuda_runtime.h>
#include <cstdint>

// Problem constants
#define B_     8
#define N_     256
#define T_     50
#define FEAT   1799
#define TOK    128
#define BN     2048       // B_*N_
#define KMAX   8          // kept EMA terms; dropped relative mass ~1e-8
#define G      16         // (b,n) rows per block
#define TF     64         // feature tile for W staging
#define NT     29         // ceil(FEAT/TF)
#define FPAD   (TF*NT)    // 1856: fbar row stride, tile-multiple, zero-padded
#define WPITCH 129        // wtile pitch (conflict-free transpose)

#define SMEM_FLOATS (G*FPAD + TF*WPITCH + G*KMAX + G + G*KMAX)
#define SMEM_BYTES  (SMEM_FLOATS * 4)

extern __shared__ float s_dyn[];

// ---------------------------------------------------------------------------
// Single fused kernel (NO __device__ globals — all scratch in smem).
// Block = G=16 (b,n) rows, 256 threads, 128 blocks.
//
// Math: reference EMA processes t = T-1..0, so
//   ema[b,n] = sum over masked t ASCENDING of 0.9 * 0.1^rank * (W feats_t + b)
//            = W * (sum_k w_k feats_{t_k}) + (sum_k w_k) * b
// truncated at KMAX=8 terms (0.1^8 relative tail << 1e-3 gate).
//
// Phase 0: mask dtype sniff + per-row scan -> (t_k, w_k).
// Phase 1: fbar[g][f] = sum_k w_k * feats[bn,t_k,f]  (coalesced, ~118MB HBM).
// Phase 2: tiled GEMM. Per 64-f tile: stage W[.,tile] transposed into smem
//   (coalesced LDG along f, conflict-free STS), then each thread (d, 8-row
//   half) accumulates with packed fma.rn.f32x2; fbar via broadcast LDS.128,
//   W via conflict-free LDS.32. All smem reads are 1-wavefront.
// ---------------------------------------------------------------------------
__global__ __launch_bounds__(256, 1)
void ema_linear_kernel(const float* __restrict__ feats,
                       const void*  __restrict__ masks,
                       const float* __restrict__ Wm,
                       const float* __restrict__ bias,
                       float* __restrict__ out) {
    float* fbar  = s_dyn;                       // G * FPAD
    float* wtile = fbar + G * FPAD;             // TF * WPITCH
    float* sw    = wtile + TF * WPITCH;         // G * KMAX
    float* ssum  = sw + G * KMAX;               // G
    int*   st    = (int*)(ssum + G);            // G * KMAX

    __shared__ unsigned int s_f32, s_gt1;

    const int tid = threadIdx.x;
    const int bn0 = blockIdx.x * G;

    // ---- Phase 0a: parallel mask dtype sniff (512 B, in-bounds for all) ----
    if (tid == 0) { s_f32 = 0u; s_gt1 = 0u; }
    __syncthreads();
    if (tid < 128) {
        unsigned int v = ((const unsigned int*)masks)[tid];
        if (v == 0x3F800000u) atomicOr(&s_f32, 1u);
        if (v > 1u)           atomicOr(&s_gt1, 1u);
    }
    __syncthreads();
    const int mode = s_f32 ? 2 : (s_gt1 ? 1 : 0);   // 2=f32, 1=u8, 0=i32

    // ---- Phase 0b: per-row mask scan -> (t_k, w_k) ----
    if (tid < G) {
        const int bn   = bn0 + tid;
        const int base = bn * T_;
        const float*         mf = (const float*)masks;
        const int*           mi = (const int*)masks;
        const unsigned char* mb = (const unsigned char*)masks;

        int   tarr[KMAX];
        float warr[KMAX];
        int   cnt = 0;
        float w   = 0.9f;
        float sum = 0.f;
        for (int t = 0; t < T_ && cnt < KMAX; ++t) {
            bool m;
            if (mode == 2)      m = (mf[base + t] != 0.f);
            else if (mode == 1) m = (mb[base + t] != 0);
            else                m = (mi[base + t] != 0);
            if (m) { tarr[cnt] = t; warr[cnt] = w; sum += w; w *= 0.1f; ++cnt; }
        }
        int tpad = (cnt > 0) ? tarr[cnt - 1] : 0;   // zero-weight dup (L1-hit)
        for (int k = cnt; k < KMAX; ++k) { tarr[k] = tpad; warr[k] = 0.f; }

#pragma unroll
        for (int k = 0; k < KMAX; ++k) {
            sw[tid * KMAX + k] = warr[k];
            st[tid * KMAX + k] = tarr[k] * FEAT;
        }
        ssum[tid] = sum;
    }
    __syncthreads();

    // ---- Phase 1: weighted time reduction into fbar (16 LDGs in flight) ----
    for (int g = 0; g < G; ++g) {
        const float* base = feats + (size_t)(bn0 + g) * (T_ * FEAT);
        float wk[KMAX]; int ok[KMAX];
#pragma unroll
        for (int k = 0; k < KMAX; ++k) { wk[k] = sw[g * KMAX + k]; ok[k] = st[g * KMAX + k]; }
        float* dst = fbar + g * FPAD;
#pragma unroll
        for (int fi = 0; fi < 4; ++fi) {
            int f0 = tid + fi * 512;
            int f1 = f0 + 256;
            bool p0 = (f0 < FEAT), p1 = (f1 < FEAT);
            float v0[KMAX], v1[KMAX];
#pragma unroll
            for (int k = 0; k < KMAX; ++k) {
                v0[k] = p0 ? __ldg(base + ok[k] + f0) : 0.f;
                v1[k] = p1 ? __ldg(base + ok[k] + f1) : 0.f;
            }
            float a0 = 0.f, a1 = 0.f;
#pragma unroll
            for (int k = 0; k < KMAX; ++k) { a0 += wk[k] * v0[k]; a1 += wk[k] * v1[k]; }
            if (f0 < FPAD) dst[f0] = a0;    // f >= FEAT writes 0 (zero pad)
            if (f1 < FPAD) dst[f1] = a1;
        }
    }

    // ---- Phase 2: tiled GEMM ----
    const int d  = tid & (TOK - 1);
    const int r0 = (tid >> 7) * 8;          // row octet
    const int w  = tid >> 5;                // warp id
    const int l  = tid & 31;                // lane

    unsigned long long acc[8];
#pragma unroll
    for (int i = 0; i < 8; ++i) acc[i] = 0ull;

    for (int tile = 0; tile < NT; ++tile) {
        const int ft = tile * TF;
        __syncthreads();   // phase-1 done (tile 0) / previous compute done
        // Stage W[., ft..ft+63] transposed: warp w covers d' = w*16..w*16+15,
        // lanes read consecutive f (coalesced), write wtile[j][d'] (no bank
        // conflicts: word stride 129).
#pragma unroll 4
        for (int i = 0; i < 16; ++i) {
            int dp = w * 16 + i;
            int f  = ft + l;
            float v0 = (f < FEAT)      ? __ldg(Wm + (size_t)dp * FEAT + f)      : 0.f;
            float v1 = (f + 32 < FEAT) ? __ldg(Wm + (size_t)dp * FEAT + f + 32) : 0.f;
            wtile[l * WPITCH + dp]        = v0;
            wtile[(l + 32) * WPITCH + dp] = v1;
        }
        __syncthreads();
        // Compute: lanes read wtile d-contiguous (conflict-free), fbar rows
        // broadcast LDS.128; 16 FFMA2 per 4-f step.
#pragma unroll
        for (int j = 0; j < TF; j += 4) {
            float w0 = wtile[(j + 0) * WPITCH + d];
            float w1 = wtile[(j + 1) * WPITCH + d];
            float w2 = wtile[(j + 2) * WPITCH + d];
            float w3 = wtile[(j + 3) * WPITCH + d];
            unsigned long long wp0, wp1;
            asm("mov.b64 %0, {%1, %2};" : "=l"(wp0) : "f"(w0), "f"(w1));
            asm("mov.b64 %0, {%1, %2};" : "=l"(wp1) : "f"(w2), "f"(w3));
#pragma unroll
            for (int g = 0; g < 8; ++g) {
                ulonglong2 fv = *(const ulonglong2*)(fbar + (r0 + g) * FPAD + ft + j);
                asm("fma.rn.f32x2 %0, %1, %2, %0;" : "+l"(acc[g]) : "l"(wp0), "l"(fv.x));
                asm("fma.rn.f32x2 %0, %1, %2, %0;" : "+l"(acc[g]) : "l"(wp1), "l"(fv.y));
            }
        }
    }

    // ---- Epilogue ----
    float res[8];
#pragma unroll
    for (int g = 0; g < 8; ++g) {
        float lo, hi;
        asm("mov.b64 {%0, %1}, %2;" : "=f"(lo), "=f"(hi) : "l"(acc[g]));
        res[g] = lo + hi;
    }
    const float bd = bias[d];
#pragma unroll
    for (int g = 0; g < 8; ++g) {
        out[(size_t)(bn0 + r0 + g) * TOK + d] = res[g] + ssum[r0 + g] * bd;
    }
}

// ---------------------------------------------------------------------------
extern "C" void kernel_launch(void* const* d_in, const int* in_sizes, int n_in,
                              void* d_out, int out_size) {
    const float* feats = (const float*)d_in[0];
    const void*  masks = d_in[1];
    const float* Wm    = (const float*)d_in[2];
    const float* bias  = (const float*)d_in[3];
    float*       out   = (float*)d_out;

    cudaFuncSetAttribute(ema_linear_kernel,
                         cudaFuncAttributeMaxDynamicSharedMemorySize, SMEM_BYTES);

    ema_linear_kernel<<<BN / G, 256, SMEM_BYTES>>>(feats, masks, Wm, bias, out);
}